// round 16
// baseline (speedup 1.0000x reference)
#include <cuda_runtime.h>
#include <cuda_fp16.h>
#include <cstdint>

#define N_NODES 50000
#define D 512
#define N_EDGES 400000
#define KTOT 1024
#define XBLKS 25000          // xconv blocks: 50000*128 vec4 / 256
#define HBLKS 1563           // hist blocks: ceil(400000/256)
#define BPBLKS 512           // bprep blocks: (KTOT/32)*(D/32)
#define NSCAN_BLKS 196       // ceil(50000/256)

// ---------------- scratch (device globals: allocation-free) ----------------
__device__ __align__(16) int   g_deg[N_NODES];
__device__ __align__(16) int   g_off[N_NODES];
__device__ __align__(16) int   g_bsum[256];
__device__ __align__(16) int   g_rank[N_EDGES];
__device__ __align__(16) int   g_csr[N_EDGES];
__device__ __align__(16) float g_bc[D];
__device__ __align__(16) __half g_A[(size_t)N_NODES * KTOT];      // [x | -mean]
__device__ __align__(16) __half g_Bt[(size_t)D * KTOT];           // Bt[n][k]

// ---------------- asm helpers ----------------
__device__ __forceinline__ uint32_t smem_u32(const void* p) {
    uint32_t a;
    asm("{ .reg .u64 t; cvta.to.shared.u64 t, %1; cvt.u32.u64 %0, t; }" : "=r"(a) : "l"(p));
    return a;
}
__device__ __forceinline__ void cp_async16(uint32_t dst, const void* src, int sz) {
    asm volatile("cp.async.cg.shared.global [%0], [%1], 16, %2;"
                 :: "r"(dst), "l"(src), "r"(sz) : "memory");
}
#define CP_COMMIT() asm volatile("cp.async.commit_group;" ::: "memory")
#define CP_WAIT2()  asm volatile("cp.async.wait_group 2;" ::: "memory")

__device__ __forceinline__ void ldm_x4(uint32_t* d, uint32_t addr) {
    asm volatile("ldmatrix.sync.aligned.m8n8.x4.shared.b16 {%0,%1,%2,%3}, [%4];"
                 : "=r"(d[0]), "=r"(d[1]), "=r"(d[2]), "=r"(d[3]) : "r"(addr));
}
__device__ __forceinline__ void mma_f16(float* c, const uint32_t* a, const uint32_t* b) {
    asm volatile("mma.sync.aligned.m16n8k16.row.col.f32.f16.f16.f32 "
                 "{%0,%1,%2,%3}, {%4,%5,%6,%7}, {%8,%9}, {%0,%1,%2,%3};"
                 : "+f"(c[0]), "+f"(c[1]), "+f"(c[2]), "+f"(c[3])
                 : "r"(a[0]), "r"(a[1]), "r"(a[2]), "r"(a[3]), "r"(b[0]), "r"(b[1]));
}

// ---------------- 1. fused xconv + hist + bprep + bias ---------------------
__global__ void fused_hx_kernel(const float* __restrict__ x, const int* __restrict__ dst,
                                const float* __restrict__ W1, const float* __restrict__ W2,
                                const float* __restrict__ b1, const float* __restrict__ b2) {
    __shared__ float tile[32][33];
    if (blockIdx.x < XBLKS) {
        int idx = blockIdx.x * 256 + threadIdx.x;      // vec4 group over x
        int row = idx >> 7;
        int c4  = (idx & 127) * 4;
        float4 v = *reinterpret_cast<const float4*>(x + (size_t)row * D + c4);
        __half2 h0 = __floats2half2_rn(v.x, v.y);
        __half2 h1 = __floats2half2_rn(v.z, v.w);
        uint2 w = make_uint2(*reinterpret_cast<uint32_t*>(&h0), *reinterpret_cast<uint32_t*>(&h1));
        *reinterpret_cast<uint2*>(g_A + (size_t)row * KTOT + c4) = w;
    } else if (blockIdx.x < XBLKS + HBLKS) {
        int e = (blockIdx.x - XBLKS) * 256 + threadIdx.x;
        if (e < N_EDGES) g_rank[e] = atomicAdd(&g_deg[dst[e]], 1);
    } else {
        int b  = blockIdx.x - XBLKS - HBLKS;           // 0..511
        int k0 = (b & 31) * 32;
        int n0 = (b >> 5) * 32;
        int tx = threadIdx.x & 31;
        int ty = threadIdx.x >> 5;
#pragma unroll
        for (int r = ty; r < 32; r += 8) {
            int kk = k0 + r, nn = n0 + tx;
            float v = (kk < D) ? (W1[kk * D + nn] + W2[kk * D + nn])
                               : W2[(kk - D) * D + nn];
            tile[r][tx] = v;
        }
        __syncthreads();
#pragma unroll
        for (int r = ty; r < 32; r += 8) {
            int wn = n0 + r, wk = k0 + tx;
            g_Bt[(size_t)wn * KTOT + wk] = __float2half_rn(tile[tx][r]);
        }
        if (b == 0) {
            int ft = threadIdx.x;
            g_bc[ft]       = b1[ft]       + b2[ft];
            g_bc[ft + 256] = b1[ft + 256] + b2[ft + 256];
        }
    }
}

// ---------------- 2. two-level exclusive scan: g_deg -> g_off, g_bsum ------
__global__ void scan1_kernel() {
    __shared__ int s[256];
    int t = threadIdx.x;
    int i = blockIdx.x * 256 + t;
    int v = (i < N_NODES) ? g_deg[i] : 0;
    s[t] = v;
    __syncthreads();
#pragma unroll
    for (int o = 1; o < 256; o <<= 1) {
        int tv = (t >= o) ? s[t - o] : 0;
        __syncthreads();
        s[t] += tv;
        __syncthreads();
    }
    if (i < N_NODES) g_off[i] = s[t] - v;
    if (t == 255) g_bsum[blockIdx.x] = s[255];
}
__global__ void scan2_kernel() {
    __shared__ int s[256];
    int t = threadIdx.x;
    int v = (t < NSCAN_BLKS) ? g_bsum[t] : 0;
    s[t] = v;
    __syncthreads();
#pragma unroll
    for (int o = 1; o < 256; o <<= 1) {
        int tv = (t >= o) ? s[t - o] : 0;
        __syncthreads();
        s[t] += tv;
        __syncthreads();
    }
    if (t < NSCAN_BLKS) g_bsum[t] = s[t] - v;
}

// ---------------- 3. fill CSR (atomic-free: rank + two-level offset) -------
__global__ void fill_kernel(const int* __restrict__ src, const int* __restrict__ dst) {
    int e = blockIdx.x * blockDim.x + threadIdx.x;
    if (e >= N_EDGES) return;
    int d = dst[e];
    int p = g_off[d] + g_bsum[d >> 8] + g_rank[e];
    g_csr[p] = src[e];
}

// ---------------- 4. aggregate: g_A[:,512:1024] = fp16(-mean) --------------
__global__ __launch_bounds__(128)
void agg_kernel() {
    int node = blockIdx.x;
    int t = threadIdx.x;
    int off = g_off[node] + g_bsum[node >> 8];
    int deg = g_deg[node];

    float ax = 0.f, ay = 0.f, az = 0.f, aw = 0.f;
    for (int e = 0; e < deg; e++) {
        int s = g_csr[off + e];
        uint2 w = *reinterpret_cast<const uint2*>(g_A + (size_t)s * KTOT + t * 4);
        float2 f0 = __half22float2(*reinterpret_cast<__half2*>(&w.x));
        float2 f1 = __half22float2(*reinterpret_cast<__half2*>(&w.y));
        ax += f0.x; ay += f0.y; az += f1.x; aw += f1.y;
    }
    float sc = (deg > 0) ? (-1.0f / (float)deg) : 0.f;
    __half2 m0 = __floats2half2_rn(ax * sc, ay * sc);
    __half2 m1 = __floats2half2_rn(az * sc, aw * sc);
    uint2 w = make_uint2(*reinterpret_cast<uint32_t*>(&m0), *reinterpret_cast<uint32_t*>(&m1));
    *reinterpret_cast<uint2*>(g_A + (size_t)node * KTOT + D + t * 4) = w;
}

// ---------------- 5. fp16 mma.sync GEMM, BM=128 BN=256, 512 threads --------
#define GEMM_THREADS 512
#define BM 128
#define BN 256
#define BKE 64                      // fp16 K elems per chunk
#define ROWB 144                    // 128B data + 16B pad
#define TILE_A (BM * ROWB)          // 18432 B
#define TILE_BB (BN * ROWB)         // 36864 B
#define STAGE_B (TILE_A + TILE_BB)  // 55296 B
#define NSTAGE 3
#define NCHUNK (KTOT / BKE)         // 16
#define GEMM_SMEM (NSTAGE * STAGE_B)  // 165888 B

__device__ __forceinline__ void load_stage(uint32_t sbase, int tid,
                                           int block_row, int block_col, int kt) {
#pragma unroll
    for (int l = 0; l < 6; l++) {
        int idx = tid + l * GEMM_THREADS;   // 0..3071
        uint32_t dstp;
        const __half* src;
        int sz = 16;
        if (idx < 1024) {                   // A: 128 rows x 8 granules
            int r = idx >> 3;
            int g = idx & 7;
            dstp = sbase + r * ROWB + g * 16;
            int grow = block_row + r;
            if (grow >= N_NODES) { grow = N_NODES - 1; sz = 0; }
            src = g_A + (size_t)grow * KTOT + kt + g * 8;
        } else {                            // B: 256 rows x 8 granules
            int rem = idx - 1024;
            int r = rem >> 3;
            int g = rem & 7;
            dstp = sbase + TILE_A + r * ROWB + g * 16;
            src = g_Bt + (size_t)(block_col + r) * KTOT + kt + g * 8;
        }
        cp_async16(dstp, src, sz);
    }
}

__global__ __launch_bounds__(GEMM_THREADS, 1)
void gemm_mma_kernel(const float* __restrict__ x, float* __restrict__ out) {
    extern __shared__ char smem[];
    const uint32_t sb0 = smem_u32(smem);
    const int tid  = threadIdx.x;
    const int wid  = tid >> 5;                    // 0..15
    const int lane = tid & 31;
    const int block_row = blockIdx.y * BM;
    const int block_col = blockIdx.x * BN;
    const int m0w = (wid & 3) * 32;               // 4 M-groups
    const int n0w = (wid >> 2) * 64;              // 4 N-groups

    float acc[2][8][4];
#pragma unroll
    for (int i = 0; i < 2; i++)
#pragma unroll
        for (int j = 0; j < 8; j++)
#pragma unroll
            for (int q = 0; q < 4; q++) acc[i][j][q] = 0.f;

#pragma unroll
    for (int s = 0; s < NSTAGE; s++) {
        load_stage(sb0 + s * STAGE_B, tid, block_row, block_col, s * BKE);
        CP_COMMIT();
    }

    const int arow    = lane & 15;
    const int acoloff = (lane >> 4) * 8;
    const int bq      = lane >> 3;
    const int brow    = ((bq >> 1) * 8) + (lane & 7);
    const int bkoff   = (bq & 1) * 8;

    for (int c = 0; c < NCHUNK; c++) {
        CP_WAIT2();
        __syncthreads();
        const uint32_t sb = sb0 + (c % NSTAGE) * STAGE_B;

#pragma unroll
        for (int ks = 0; ks < 4; ks++) {
            uint32_t a[2][4], b[8][2];
#pragma unroll
            for (int i = 0; i < 2; i++) {
                uint32_t ad = sb + (m0w + i * 16 + arow) * ROWB + (ks * 16 + acoloff) * 2;
                ldm_x4(a[i], ad);
            }
#pragma unroll
            for (int jj = 0; jj < 4; jj++) {
                uint32_t bd = sb + TILE_A + (n0w + jj * 16 + brow) * ROWB + (ks * 16 + bkoff) * 2;
                uint32_t r4[4];
                ldm_x4(r4, bd);
                b[jj*2][0] = r4[0]; b[jj*2][1] = r4[1];
                b[jj*2+1][0] = r4[2]; b[jj*2+1][1] = r4[3];
            }
#pragma unroll
            for (int i = 0; i < 2; i++)
#pragma unroll
                for (int j = 0; j < 8; j++)
                    mma_f16(acc[i][j], a[i], b[j]);
        }
        __syncthreads();
        if (c + NSTAGE < NCHUNK)
            load_stage(sb, tid, block_row, block_col, (c + NSTAGE) * BKE);
        CP_COMMIT();
    }

    // epilogue: bias + degree-0 passthrough
#pragma unroll
    for (int i = 0; i < 2; i++) {
        int r0 = block_row + m0w + i * 16 + (lane >> 2);
        int r1 = r0 + 8;
        bool v0 = r0 < N_NODES, v1 = r1 < N_NODES;
        int c0 = v0 ? g_deg[r0] : 0;
        int c1 = v1 ? g_deg[r1] : 0;
#pragma unroll
        for (int j = 0; j < 8; j++) {
            int col = block_col + n0w + j * 8 + (lane & 3) * 2;
            float b0 = g_bc[col], b1 = g_bc[col + 1];
            if (v0) {
                float2 o;
                if (c0 > 0) { o.x = acc[i][j][0] + b0; o.y = acc[i][j][1] + b1; }
                else { o = *reinterpret_cast<const float2*>(x + (size_t)r0 * D + col); }
                *reinterpret_cast<float2*>(out + (size_t)r0 * D + col) = o;
            }
            if (v1) {
                float2 o;
                if (c1 > 0) { o.x = acc[i][j][2] + b0; o.y = acc[i][j][3] + b1; }
                else { o = *reinterpret_cast<const float2*>(x + (size_t)r1 * D + col); }
                *reinterpret_cast<float2*>(out + (size_t)r1 * D + col) = o;
            }
        }
    }
}

// ---------------- launch ----------------
extern "C" void kernel_launch(void* const* d_in, const int* in_sizes, int n_in,
                              void* d_out, int out_size) {
    const float* x   = (const float*)d_in[0];
    const int*   src = (const int*)d_in[1];
    const int*   dst = (const int*)d_in[2];
    const float* W1  = (const float*)d_in[3];
    const float* b1  = (const float*)d_in[4];
    const float* W2  = (const float*)d_in[5];
    const float* b2  = (const float*)d_in[6];
    float* out = (float*)d_out;

    cudaFuncSetAttribute(gemm_mma_kernel, cudaFuncAttributeMaxDynamicSharedMemorySize, GEMM_SMEM);

    void *p_deg = nullptr;
    cudaGetSymbolAddress(&p_deg, g_deg);
    cudaMemsetAsync(p_deg, 0, N_NODES * sizeof(int));

    fused_hx_kernel<<<XBLKS + HBLKS + BPBLKS, 256>>>(x, dst, W1, W2, b1, b2);
    scan1_kernel<<<NSCAN_BLKS, 256>>>();
    scan2_kernel<<<1, 256>>>();
    fill_kernel<<<(N_EDGES + 255) / 256, 256>>>(src, dst);
    agg_kernel<<<N_NODES, 128>>>();
    {
        dim3 grid(D / BN, (N_NODES + BM - 1) / BM);
        gemm_mma_kernel<<<grid, GEMM_THREADS, GEMM_SMEM>>>(x, out);
    }
}

// round 17
// speedup vs baseline: 1.1103x; 1.1103x over previous
#include <cuda_runtime.h>
#include <cuda_fp16.h>
#include <cstdint>

#define N_NODES 50000
#define D 512
#define N_EDGES 400000
#define KTOT 1024
#define XBLKS 25000          // xconv blocks: 50000*128 vec4 / 256
#define HBLKS 1563           // hist blocks: ceil(400000/256)
#define BPBLKS 512           // bprep blocks: (KTOT/32)*(D/32)
#define NSCAN_BLKS 196       // ceil(50000/256)

// ---------------- scratch (device globals: allocation-free) ----------------
__device__ __align__(16) int   g_deg[N_NODES];
__device__ __align__(16) int   g_off[N_NODES];
__device__ __align__(16) int   g_bsum[256];
__device__ __align__(16) int   g_rank[N_EDGES];
__device__ __align__(16) int   g_csr[N_EDGES];
__device__ __align__(16) float g_bc[D];
__device__ __align__(16) __half g_A[(size_t)N_NODES * KTOT];      // [x | -mean]
__device__ __align__(16) __half g_Bt[(size_t)D * KTOT];           // Bt[n][k]

// ---------------- asm helpers ----------------
__device__ __forceinline__ uint32_t smem_u32(const void* p) {
    uint32_t a;
    asm("{ .reg .u64 t; cvta.to.shared.u64 t, %1; cvt.u32.u64 %0, t; }" : "=r"(a) : "l"(p));
    return a;
}
__device__ __forceinline__ void cp_async16(uint32_t dst, const void* src, int sz) {
    asm volatile("cp.async.cg.shared.global [%0], [%1], 16, %2;"
                 :: "r"(dst), "l"(src), "r"(sz) : "memory");
}
#define CP_COMMIT() asm volatile("cp.async.commit_group;" ::: "memory")
#define CP_WAIT2()  asm volatile("cp.async.wait_group 2;" ::: "memory")

__device__ __forceinline__ void ldm_x4(uint32_t* d, uint32_t addr) {
    asm volatile("ldmatrix.sync.aligned.m8n8.x4.shared.b16 {%0,%1,%2,%3}, [%4];"
                 : "=r"(d[0]), "=r"(d[1]), "=r"(d[2]), "=r"(d[3]) : "r"(addr));
}
__device__ __forceinline__ void mma_f16(float* c, const uint32_t* a, const uint32_t* b) {
    asm volatile("mma.sync.aligned.m16n8k16.row.col.f32.f16.f16.f32 "
                 "{%0,%1,%2,%3}, {%4,%5,%6,%7}, {%8,%9}, {%0,%1,%2,%3};"
                 : "+f"(c[0]), "+f"(c[1]), "+f"(c[2]), "+f"(c[3])
                 : "r"(a[0]), "r"(a[1]), "r"(a[2]), "r"(a[3]), "r"(b[0]), "r"(b[1]));
}

// ---------------- 1. fused xconv + hist + bprep + bias ---------------------
__global__ void fused_hx_kernel(const float* __restrict__ x, const int* __restrict__ dst,
                                const float* __restrict__ W1, const float* __restrict__ W2,
                                const float* __restrict__ b1, const float* __restrict__ b2) {
    __shared__ float tile[32][33];
    if (blockIdx.x < XBLKS) {
        int idx = blockIdx.x * 256 + threadIdx.x;      // vec4 group over x
        int row = idx >> 7;
        int c4  = (idx & 127) * 4;
        float4 v = *reinterpret_cast<const float4*>(x + (size_t)row * D + c4);
        __half2 h0 = __floats2half2_rn(v.x, v.y);
        __half2 h1 = __floats2half2_rn(v.z, v.w);
        uint2 w = make_uint2(*reinterpret_cast<uint32_t*>(&h0), *reinterpret_cast<uint32_t*>(&h1));
        *reinterpret_cast<uint2*>(g_A + (size_t)row * KTOT + c4) = w;
    } else if (blockIdx.x < XBLKS + HBLKS) {
        int e = (blockIdx.x - XBLKS) * 256 + threadIdx.x;
        if (e < N_EDGES) g_rank[e] = atomicAdd(&g_deg[dst[e]], 1);
    } else {
        int b  = blockIdx.x - XBLKS - HBLKS;           // 0..511
        int k0 = (b & 31) * 32;
        int n0 = (b >> 5) * 32;
        int tx = threadIdx.x & 31;
        int ty = threadIdx.x >> 5;
#pragma unroll
        for (int r = ty; r < 32; r += 8) {
            int kk = k0 + r, nn = n0 + tx;
            float v = (kk < D) ? (W1[kk * D + nn] + W2[kk * D + nn])
                               : W2[(kk - D) * D + nn];
            tile[r][tx] = v;
        }
        __syncthreads();
#pragma unroll
        for (int r = ty; r < 32; r += 8) {
            int wn = n0 + r, wk = k0 + tx;
            g_Bt[(size_t)wn * KTOT + wk] = __float2half_rn(tile[tx][r]);
        }
        if (b == 0) {
            int ft = threadIdx.x;
            g_bc[ft]       = b1[ft]       + b2[ft];
            g_bc[ft + 256] = b1[ft + 256] + b2[ft + 256];
        }
    }
}

// ---------------- 2. two-level exclusive scan: g_deg -> g_off, g_bsum ------
__global__ void scan1_kernel() {
    __shared__ int s[256];
    int t = threadIdx.x;
    int i = blockIdx.x * 256 + t;
    int v = (i < N_NODES) ? g_deg[i] : 0;
    s[t] = v;
    __syncthreads();
#pragma unroll
    for (int o = 1; o < 256; o <<= 1) {
        int tv = (t >= o) ? s[t - o] : 0;
        __syncthreads();
        s[t] += tv;
        __syncthreads();
    }
    if (i < N_NODES) g_off[i] = s[t] - v;
    if (t == 255) g_bsum[blockIdx.x] = s[255];
}
__global__ void scan2_kernel() {
    __shared__ int s[256];
    int t = threadIdx.x;
    int v = (t < NSCAN_BLKS) ? g_bsum[t] : 0;
    s[t] = v;
    __syncthreads();
#pragma unroll
    for (int o = 1; o < 256; o <<= 1) {
        int tv = (t >= o) ? s[t - o] : 0;
        __syncthreads();
        s[t] += tv;
        __syncthreads();
    }
    if (t < NSCAN_BLKS) g_bsum[t] = s[t] - v;
}

// ---------------- 3. fill CSR (atomic-free, int4 vectorized) ---------------
__global__ void fill_kernel(const int* __restrict__ src, const int* __restrict__ dst) {
    int i = blockIdx.x * blockDim.x + threadIdx.x;     // over N_EDGES/4
    if (i >= N_EDGES / 4) return;
    int4 d4 = reinterpret_cast<const int4*>(dst)[i];
    int4 r4 = reinterpret_cast<const int4*>(g_rank)[i];
    int4 s4 = reinterpret_cast<const int4*>(src)[i];
    g_csr[g_off[d4.x] + g_bsum[d4.x >> 8] + r4.x] = s4.x;
    g_csr[g_off[d4.y] + g_bsum[d4.y >> 8] + r4.y] = s4.y;
    g_csr[g_off[d4.z] + g_bsum[d4.z >> 8] + r4.z] = s4.z;
    g_csr[g_off[d4.w] + g_bsum[d4.w >> 8] + r4.w] = s4.w;
}

// ---------------- 4. aggregate: g_A[:,512:1024] = fp16(-mean) --------------
__global__ __launch_bounds__(128)
void agg_kernel() {
    int node = blockIdx.x;
    int t = threadIdx.x;
    int off = g_off[node] + g_bsum[node >> 8];
    int deg = g_deg[node];

    float ax = 0.f, ay = 0.f, az = 0.f, aw = 0.f;
    for (int e = 0; e < deg; e++) {
        int s = g_csr[off + e];
        uint2 w = *reinterpret_cast<const uint2*>(g_A + (size_t)s * KTOT + t * 4);
        float2 f0 = __half22float2(*reinterpret_cast<__half2*>(&w.x));
        float2 f1 = __half22float2(*reinterpret_cast<__half2*>(&w.y));
        ax += f0.x; ay += f0.y; az += f1.x; aw += f1.y;
    }
    float sc = (deg > 0) ? (-1.0f / (float)deg) : 0.f;
    __half2 m0 = __floats2half2_rn(ax * sc, ay * sc);
    __half2 m1 = __floats2half2_rn(az * sc, aw * sc);
    uint2 w = make_uint2(*reinterpret_cast<uint32_t*>(&m0), *reinterpret_cast<uint32_t*>(&m1));
    *reinterpret_cast<uint2*>(g_A + (size_t)node * KTOT + D + t * 4) = w;
}

// ---------------- 5. fp16 mma.sync GEMM, BKE=64 (r12/r15 best config) ------
#define BM 128
#define BN 128
#define BKE 64                      // fp16 K elems per chunk
#define ROWB 144                    // 128B data + 16B pad
#define TILE_B (128 * ROWB)         // 18432 B
#define STAGE_B (2 * TILE_B)        // 36864 B (A, B)
#define NSTAGE 3
#define NCHUNK (KTOT / BKE)         // 16
#define GEMM_SMEM (NSTAGE * STAGE_B)

__device__ __forceinline__ void load_stage(uint32_t sbase, int tid,
                                           int block_row, int block_col, int kt) {
#pragma unroll
    for (int l = 0; l < 8; l++) {
        int idx  = tid + l * 256;        // 0..2047
        int tile = idx >> 10;            // 0:A 1:B
        int rem  = idx & 1023;
        int r    = rem >> 3;             // row 0..127
        int g    = rem & 7;              // 16B granule (8 per 128B row)
        uint32_t dstp = sbase + tile * TILE_B + r * ROWB + g * 16;
        const __half* src;
        int sz = 16;
        if (tile == 0) {
            int grow = block_row + r;
            if (grow >= N_NODES) { grow = N_NODES - 1; sz = 0; }
            src = g_A + (size_t)grow * KTOT + kt + g * 8;
        } else {
            src = g_Bt + (size_t)(block_col + r) * KTOT + kt + g * 8;
        }
        cp_async16(dstp, src, sz);
    }
}

__global__ __launch_bounds__(256, 2)
void gemm_mma_kernel(const float* __restrict__ x, float* __restrict__ out) {
    extern __shared__ char smem[];
    const uint32_t sb0 = smem_u32(smem);
    const int tid  = threadIdx.x;
    const int wid  = tid >> 5;
    const int lane = tid & 31;
    const int block_row = blockIdx.y * BM;
    const int block_col = blockIdx.x * BN;
    const int m0w = (wid & 3) * 32;
    const int n0w = (wid >> 2) * 64;

    float acc[2][8][4];
#pragma unroll
    for (int i = 0; i < 2; i++)
#pragma unroll
        for (int j = 0; j < 8; j++)
#pragma unroll
            for (int q = 0; q < 4; q++) acc[i][j][q] = 0.f;

#pragma unroll
    for (int s = 0; s < NSTAGE; s++) {
        load_stage(sb0 + s * STAGE_B, tid, block_row, block_col, s * BKE);
        CP_COMMIT();
    }

    const int arow    = lane & 15;
    const int acoloff = (lane >> 4) * 8;
    const int bq      = lane >> 3;
    const int brow    = ((bq >> 1) * 8) + (lane & 7);
    const int bkoff   = (bq & 1) * 8;

    for (int c = 0; c < NCHUNK; c++) {
        CP_WAIT2();
        __syncthreads();
        const uint32_t sb = sb0 + (c % NSTAGE) * STAGE_B;

#pragma unroll
        for (int ks = 0; ks < 4; ks++) {
            uint32_t a[2][4], b[8][2];
#pragma unroll
            for (int i = 0; i < 2; i++) {
                uint32_t ad = sb + (m0w + i * 16 + arow) * ROWB + (ks * 16 + acoloff) * 2;
                ldm_x4(a[i], ad);
            }
#pragma unroll
            for (int jj = 0; jj < 4; jj++) {
                uint32_t bd = sb + TILE_B + (n0w + jj * 16 + brow) * ROWB + (ks * 16 + bkoff) * 2;
                uint32_t r4[4];
                ldm_x4(r4, bd);
                b[jj*2][0] = r4[0]; b[jj*2][1] = r4[1];
                b[jj*2+1][0] = r4[2]; b[jj*2+1][1] = r4[3];
            }
#pragma unroll
            for (int i = 0; i < 2; i++)
#pragma unroll
                for (int j = 0; j < 8; j++)
                    mma_f16(acc[i][j], a[i], b[j]);
        }
        __syncthreads();
        if (c + NSTAGE < NCHUNK)
            load_stage(sb, tid, block_row, block_col, (c + NSTAGE) * BKE);
        CP_COMMIT();
    }

    // epilogue: bias + degree-0 passthrough
#pragma unroll
    for (int i = 0; i < 2; i++) {
        int r0 = block_row + m0w + i * 16 + (lane >> 2);
        int r1 = r0 + 8;
        bool v0 = r0 < N_NODES, v1 = r1 < N_NODES;
        int c0 = v0 ? g_deg[r0] : 0;
        int c1 = v1 ? g_deg[r1] : 0;
#pragma unroll
        for (int j = 0; j < 8; j++) {
            int col = block_col + n0w + j * 8 + (lane & 3) * 2;
            float b0 = g_bc[col], b1 = g_bc[col + 1];
            if (v0) {
                float2 o;
                if (c0 > 0) { o.x = acc[i][j][0] + b0; o.y = acc[i][j][1] + b1; }
                else { o = *reinterpret_cast<const float2*>(x + (size_t)r0 * D + col); }
                *reinterpret_cast<float2*>(out + (size_t)r0 * D + col) = o;
            }
            if (v1) {
                float2 o;
                if (c1 > 0) { o.x = acc[i][j][2] + b0; o.y = acc[i][j][3] + b1; }
                else { o = *reinterpret_cast<const float2*>(x + (size_t)r1 * D + col); }
                *reinterpret_cast<float2*>(out + (size_t)r1 * D + col) = o;
            }
        }
    }
}

// ---------------- launch ----------------
extern "C" void kernel_launch(void* const* d_in, const int* in_sizes, int n_in,
                              void* d_out, int out_size) {
    const float* x   = (const float*)d_in[0];
    const int*   src = (const int*)d_in[1];
    const int*   dst = (const int*)d_in[2];
    const float* W1  = (const float*)d_in[3];
    const float* b1  = (const float*)d_in[4];
    const float* W2  = (const float*)d_in[5];
    const float* b2  = (const float*)d_in[6];
    float* out = (float*)d_out;

    cudaFuncSetAttribute(gemm_mma_kernel, cudaFuncAttributeMaxDynamicSharedMemorySize, GEMM_SMEM);

    void *p_deg = nullptr;
    cudaGetSymbolAddress(&p_deg, g_deg);
    cudaMemsetAsync(p_deg, 0, N_NODES * sizeof(int));

    fused_hx_kernel<<<XBLKS + HBLKS + BPBLKS, 256>>>(x, dst, W1, W2, b1, b2);
    scan1_kernel<<<NSCAN_BLKS, 256>>>();
    scan2_kernel<<<1, 256>>>();
    fill_kernel<<<(N_EDGES / 4 + 255) / 256, 256>>>(src, dst);
    agg_kernel<<<N_NODES, 128>>>();
    {
        dim3 grid(D / BN, (N_NODES + BM - 1) / BM);
        gemm_mma_kernel<<<grid, 256, GEMM_SMEM>>>(x, out);
    }
}